// round 2
// baseline (speedup 1.0000x reference)
#include <cuda_runtime.h>
#include <cstdint>

#define S_ 4
#define B_ 2
#define N_ 1024
#define D_ 1024
#define H_ 16
#define DH_ 64

// ---------------- device scratch (static: no allocations allowed) ----------
__device__ float g_q[S_ * B_ * N_ * D_];                  // [s][b*N+n][h*64+dh]  32MB
__device__ float g_k[S_ * B_ * N_ * D_];                  // 32MB
__device__ float g_v[S_ * B_ * N_ * D_];                  // 32MB
__device__ float g_P[(size_t)S_ * B_ * H_ * N_ * N_];     // [s][b][h][i][j]     512MB
__device__ float g_comb[B_ * N_ * D_];                    // combined            8MB
__device__ float g_meanx[B_ * D_];
__device__ float g_scalars[16];  // [0..7]=w_sb (b*4+s), [8..11]=gw[s]/H, [12]=scale/temp

// ---------------- column mean of x over N ----------------------------------
__global__ void colmean_k(const float* __restrict__ x) {
    int idx = blockIdx.x * 256 + threadIdx.x;   // 0..2047
    int b = idx >> 10, d = idx & 1023;
    float sum = 0.f;
    const float* xp = x + (long long)b * N_ * D_ + d;
    for (int n = 0; n < N_; n++) sum += xp[(long long)n * D_];
    g_meanx[idx] = sum * (1.0f / N_);
}

// ---------------- gate: coh, gw, fused scalars ------------------------------
__global__ void gate_k(const float* __restrict__ Wg, const float* __restrict__ bg,
                       const float* __restrict__ hyp_w, const float* __restrict__ temp_p) {
    __shared__ float cohs[8];
    int tid = threadIdx.x;
    int w = tid >> 5, lane = tid & 31;
    if (w < 8) {
        int b = w >> 2, s = w & 3;
        float sum = 0.f;
        for (int d = lane; d < D_; d += 32)
            sum += g_meanx[b * D_ + d] * Wg[s * D_ + d];
        for (int o = 16; o; o >>= 1) sum += __shfl_xor_sync(0xffffffffu, sum, o);
        if (lane == 0) cohs[w] = 1.0f / (1.0f + expf(-(sum + bg[s])));
    }
    __syncthreads();
    if (tid == 0) {
        float t = fminf(fmaxf(temp_p[0], 0.1f), 10.0f);
        float e[S_], mx = -1e30f;
        for (int s = 0; s < S_; s++) { e[s] = hyp_w[s] / t; mx = fmaxf(mx, e[s]); }
        float den = 0.f;
        for (int s = 0; s < S_; s++) { e[s] = expf(e[s] - mx); den += e[s]; }
        for (int s = 0; s < S_; s++) {
            float gw = e[s] / den;
            g_scalars[8 + s] = gw / (float)H_;
            for (int b = 0; b < B_; b++)
                g_scalars[b * 4 + s] = gw * cohs[b * 4 + s];
        }
        g_scalars[12] = 0.125f / t;   // DH^-0.5 / temp
    }
}

// ---------------- generic 128x128x8 SGEMM, C = alpha*A*op(B) + beta*C + bias
// bT=1: B is [Ncols,K] row-major (NT).  bT=0: B is [K,Ncols] row-major (NN).
// mode 0: linear batch strides. mode 1: QK^T slices. mode 2: P*V slices.
__global__ void __launch_bounds__(256) sgemm_k(
    const float* __restrict__ A, const float* __restrict__ B, float* __restrict__ C,
    int M, int Ncols, int K, int lda, int ldb, int ldc,
    long long sA, long long sB, long long sC,
    int mode, int s_fixed, const float* alpha_ptr, float beta,
    const float* __restrict__ bias, int bT)
{
    int z = blockIdx.z;
    long long offA, offB, offC;
    if (mode == 0) {
        offA = z * sA; offB = z * sB; offC = z * sC;
    } else if (mode == 1) {            // dots: z = ((s*B+b)*H+h)
        int s = z >> 5, r = z & 31, b = r >> 4, h = r & 15;
        offA = ((long long)(s * B_ + b) * N_) * D_ + h * DH_;
        offB = offA;                   // k has identical layout
        offC = (long long)z * N_ * N_;
    } else {                            // PV: z = b*H + h, s = s_fixed
        int b = z >> 4, h = z & 15, s = s_fixed;
        offA = (long long)((s * B_ + b) * H_ + h) * N_ * N_;
        offB = ((long long)(s * B_ + b) * N_) * D_ + h * DH_;
        offC = (long long)b * N_ * D_ + h * DH_;
    }
    const float* Ab = A + offA;
    const float* Bb = B + offB;
    float* Cb = C + offC;

    __shared__ float As[8][128];
    __shared__ float Bs[8][128];
    int tid = threadIdx.x;
    int m0 = blockIdx.y * 128, n0 = blockIdx.x * 128;
    float acc[8][8];
    #pragma unroll
    for (int i = 0; i < 8; i++)
        #pragma unroll
        for (int j = 0; j < 8; j++) acc[i][j] = 0.f;

    int arow = tid >> 1;
    int acol = (tid & 1) << 2;
    int tx = tid & 15, ty = tid >> 4;

    for (int k0 = 0; k0 < K; k0 += 8) {
        float4 av = *(const float4*)(Ab + (long long)(m0 + arow) * lda + k0 + acol);
        As[acol + 0][arow] = av.x; As[acol + 1][arow] = av.y;
        As[acol + 2][arow] = av.z; As[acol + 3][arow] = av.w;
        if (bT) {
            float4 bv = *(const float4*)(Bb + (long long)(n0 + arow) * ldb + k0 + acol);
            Bs[acol + 0][arow] = bv.x; Bs[acol + 1][arow] = bv.y;
            Bs[acol + 2][arow] = bv.z; Bs[acol + 3][arow] = bv.w;
        } else {
            int br = tid >> 5;
            int bc = (tid & 31) << 2;
            float4 bv = make_float4(0.f, 0.f, 0.f, 0.f);
            if (n0 + bc + 3 < Ncols)
                bv = *(const float4*)(Bb + (long long)(k0 + br) * ldb + n0 + bc);
            *(float4*)&Bs[br][bc] = bv;
        }
        __syncthreads();
        #pragma unroll
        for (int kk = 0; kk < 8; kk++) {
            float a[8], bb[8];
            #pragma unroll
            for (int i = 0; i < 8; i++) a[i] = As[kk][ty * 8 + i];
            #pragma unroll
            for (int j = 0; j < 8; j++) bb[j] = Bs[kk][tx * 8 + j];
            #pragma unroll
            for (int i = 0; i < 8; i++)
                #pragma unroll
                for (int j = 0; j < 8; j++)
                    acc[i][j] += a[i] * bb[j];
        }
        __syncthreads();
    }

    float alpha = alpha_ptr ? *alpha_ptr : 1.0f;
    #pragma unroll
    for (int i = 0; i < 8; i++) {
        int row = m0 + ty * 8 + i;
        #pragma unroll
        for (int j = 0; j < 8; j++) {
            int col = n0 + tx * 8 + j;
            if (row < M && col < Ncols) {
                long long idx = (long long)row * ldc + col;
                float vv = alpha * acc[i][j];
                if (beta != 0.f) vv += beta * Cb[idx];
                if (bias) vv += bias[col];
                Cb[idx] = vv;
            }
        }
    }
}

// ---------------- softmax over P rows + gate-fold + attn-mean accumulation --
// block = one (b,i) row group: owns d_out attn row exclusively (no atomics)
__global__ void __launch_bounds__(256) softmax_attn_k(float* __restrict__ P,
                                                      float* __restrict__ Aout) {
    int bi = blockIdx.x;
    int b = bi >> 10, i = bi & 1023;
    int tid = threadIdx.x;
    __shared__ float red[8];
    float aacc0 = 0.f, aacc1 = 0.f, aacc2 = 0.f, aacc3 = 0.f;

    for (int s = 0; s < S_; s++) {
        float ga = g_scalars[8 + s];
        float wsb = g_scalars[b * 4 + s];
        for (int h = 0; h < H_; h++) {
            float* row = P + ((long long)((s * B_ + b) * H_ + h) * N_ + i) * N_;
            float v0 = row[tid], v1 = row[tid + 256], v2 = row[tid + 512], v3 = row[tid + 768];
            float mx = fmaxf(fmaxf(v0, v1), fmaxf(v2, v3));
            for (int o = 16; o; o >>= 1) mx = fmaxf(mx, __shfl_xor_sync(0xffffffffu, mx, o));
            if ((tid & 31) == 0) red[tid >> 5] = mx;
            __syncthreads();
            mx = fmaxf(fmaxf(fmaxf(red[0], red[1]), fmaxf(red[2], red[3])),
                       fmaxf(fmaxf(red[4], red[5]), fmaxf(red[6], red[7])));
            __syncthreads();
            v0 = __expf(v0 - mx); v1 = __expf(v1 - mx);
            v2 = __expf(v2 - mx); v3 = __expf(v3 - mx);
            float sm = v0 + v1 + v2 + v3;
            for (int o = 16; o; o >>= 1) sm += __shfl_xor_sync(0xffffffffu, sm, o);
            if ((tid & 31) == 0) red[tid >> 5] = sm;
            __syncthreads();
            sm = red[0] + red[1] + red[2] + red[3] + red[4] + red[5] + red[6] + red[7];
            __syncthreads();
            float inv = 1.0f / sm;
            v0 *= inv; v1 *= inv; v2 *= inv; v3 *= inv;
            aacc0 += ga * v0; aacc1 += ga * v1; aacc2 += ga * v2; aacc3 += ga * v3;
            row[tid] = wsb * v0; row[tid + 256] = wsb * v1;
            row[tid + 512] = wsb * v2; row[tid + 768] = wsb * v3;
        }
    }
    long long base = (long long)bi * N_;
    Aout[base + tid] = aacc0; Aout[base + tid + 256] = aacc1;
    Aout[base + tid + 512] = aacc2; Aout[base + tid + 768] = aacc3;
}

// ---------------- launch --------------------------------------------------
extern "C" void kernel_launch(void* const* d_in, const int* in_sizes, int n_in,
                              void* d_out, int out_size) {
    const float* x     = (const float*)d_in[0];
    const float* Wq    = (const float*)d_in[1];
    const float* Wk    = (const float*)d_in[2];
    const float* Wv    = (const float*)d_in[3];
    const float* Wg    = (const float*)d_in[4];
    const float* bg    = (const float*)d_in[5];
    const float* Wo    = (const float*)d_in[6];
    const float* bo    = (const float*)d_in[7];
    const float* hyp_w = (const float*)d_in[8];
    const float* temp  = (const float*)d_in[9];
    float* out = (float*)d_out;

    float *q, *k, *v, *P, *comb, *scal;
    cudaGetSymbolAddress((void**)&q, g_q);
    cudaGetSymbolAddress((void**)&k, g_k);
    cudaGetSymbolAddress((void**)&v, g_v);
    cudaGetSymbolAddress((void**)&P, g_P);
    cudaGetSymbolAddress((void**)&comb, g_comb);
    cudaGetSymbolAddress((void**)&scal, g_scalars);

    const int M = B_ * N_;                       // 2048
    const long long DD = (long long)D_ * D_;     // weight per-s stride
    const long long QS = (long long)M * D_;      // qkv per-s stride

    colmean_k<<<8, 256>>>(x);
    gate_k<<<1, 256>>>(Wg, bg, hyp_w, temp);

    // QKV projections: z = s, NT GEMM, 2048x1024x1024
    sgemm_k<<<dim3(8, 16, 4), 256>>>(x, Wq, q, M, D_, D_, D_, D_, D_,
                                     0, DD, QS, 0, 0, nullptr, 0.f, nullptr, 1);
    sgemm_k<<<dim3(8, 16, 4), 256>>>(x, Wk, k, M, D_, D_, D_, D_, D_,
                                     0, DD, QS, 0, 0, nullptr, 0.f, nullptr, 1);
    sgemm_k<<<dim3(8, 16, 4), 256>>>(x, Wv, v, M, D_, D_, D_, D_, D_,
                                     0, DD, QS, 0, 0, nullptr, 0.f, nullptr, 1);

    // dots: z over 128 (s,b,h) slices, 1024x1024x64 NT, alpha = scale/temp (device)
    sgemm_k<<<dim3(8, 8, 128), 256>>>(q, k, P, N_, N_, DH_, D_, D_, N_,
                                      0, 0, 0, 1, 0, scal + 12, 0.f, nullptr, 1);

    // softmax + gate-fold + attn-mean -> second half of d_out
    softmax_attn_k<<<B_ * N_, 256>>>(P, out + (long long)B_ * N_ * D_);

    // P @ V, accumulated over s into combined (1024x64x1024 NN per slice)
    for (int s = 0; s < S_; s++)
        sgemm_k<<<dim3(1, 8, 32), 256>>>(P, v, comb, N_, DH_, N_, N_, D_, D_,
                                         0, 0, 0, 2, s, nullptr,
                                         (s == 0) ? 0.f : 1.f, nullptr, 0);

    // y = combined @ Wo^T + bo -> first half of d_out
    sgemm_k<<<dim3(8, 16, 1), 256>>>(comb, Wo, out, M, D_, D_, D_, D_, D_,
                                     0, 0, 0, 0, 0, nullptr, 0.f, bo, 1);
}

// round 4
// speedup vs baseline: 3.2538x; 3.2538x over previous
#include <cuda_runtime.h>
#include <cstdint>

#define S_ 4
#define B_ 2
#define N_ 1024
#define D_ 1024
#define H_ 16
#define DH_ 64

// ---------------- device scratch (no allocations allowed) -------------------
__device__ float g_q[S_ * B_ * N_ * D_];                  // [s][b*N+n][e]      32MB
__device__ float g_k[S_ * B_ * N_ * D_];                  // 32MB
__device__ float g_vT[S_ * B_ * N_ * D_];                 // [s][b][h][dh][n]   32MB
__device__ float g_P[(size_t)S_ * B_ * H_ * N_ * N_];     // [s][b][h][i][j]    512MB
__device__ float g_comb[B_ * N_ * D_];                    // 8MB
__device__ float g_meanx[B_ * D_];
__device__ float g_scalars[16];  // [0..7]=gw*coh (b*4+s), [8..11]=gw/H, [12]=scale/temp

// ---------------- helpers ----------------------------------------------------
__device__ __forceinline__ uint32_t smem_u32(const void* p) {
    uint32_t a;
    asm("{ .reg .u64 t; cvta.to.shared.u64 t, %1; cvt.u32.u64 %0, t; }" : "=r"(a) : "l"(p));
    return a;
}
__device__ __forceinline__ uint32_t f2tf(float f) {
    uint32_t u;
    asm("cvt.rna.tf32.f32 %0, %1;" : "=r"(u) : "f"(f));
    return u;
}
__device__ __forceinline__ void cp16(uint32_t dst, const float* src) {
    asm volatile("cp.async.ca.shared.global [%0], [%1], 16;" :: "r"(dst), "l"(src) : "memory");
}
__device__ __forceinline__ void mma1688(float* d, const uint32_t* a, const uint32_t* b) {
    asm volatile(
        "mma.sync.aligned.m16n8k8.row.col.f32.tf32.tf32.f32 "
        "{%0,%1,%2,%3}, {%4,%5,%6,%7}, {%8,%9}, {%0,%1,%2,%3};"
        : "+f"(d[0]), "+f"(d[1]), "+f"(d[2]), "+f"(d[3])
        : "r"(a[0]), "r"(a[1]), "r"(a[2]), "r"(a[3]), "r"(b[0]), "r"(b[1]));
}

// ---------------- column mean of x over N ----------------------------------
__global__ void colmean_k(const float* __restrict__ x) {
    int idx = blockIdx.x * 256 + threadIdx.x;
    int b = idx >> 10, d = idx & 1023;
    float sum = 0.f;
    const float* xp = x + (long long)b * N_ * D_ + d;
    for (int n = 0; n < N_; n++) sum += xp[(long long)n * D_];
    g_meanx[idx] = sum * (1.0f / N_);
}

// ---------------- gate: coh, gw, fused scalars ------------------------------
__global__ void gate_k(const float* __restrict__ Wg, const float* __restrict__ bg,
                       const float* __restrict__ hyp_w, const float* __restrict__ temp_p) {
    __shared__ float cohs[8];
    int tid = threadIdx.x;
    int w = tid >> 5, lane = tid & 31;
    if (w < 8) {
        int b = w >> 2, s = w & 3;
        float sum = 0.f;
        for (int d = lane; d < D_; d += 32)
            sum += g_meanx[b * D_ + d] * Wg[s * D_ + d];
        for (int o = 16; o; o >>= 1) sum += __shfl_xor_sync(0xffffffffu, sum, o);
        if (lane == 0) cohs[w] = 1.0f / (1.0f + expf(-(sum + bg[s])));
    }
    __syncthreads();
    if (tid == 0) {
        float t = fminf(fmaxf(temp_p[0], 0.1f), 10.0f);
        float e[S_], mx = -1e30f;
        for (int s = 0; s < S_; s++) { e[s] = hyp_w[s] / t; mx = fmaxf(mx, e[s]); }
        float den = 0.f;
        for (int s = 0; s < S_; s++) { e[s] = expf(e[s] - mx); den += e[s]; }
        for (int s = 0; s < S_; s++) {
            float gw = e[s] / den;
            g_scalars[8 + s] = gw / (float)H_;
            for (int b = 0; b < B_; b++)
                g_scalars[b * 4 + s] = gw * cohs[b * 4 + s];
        }
        g_scalars[12] = 0.125f / t;   // DH^-0.5 / temp
    }
}

// ---------------- HMMA tf32 GEMM: C[128,BN] = A @ B^T -----------------------
// MODE 0: C = A @ W^T (+bias). z: Bm += z*sB, C += z*sC. A shared across z.
//         TRANSC: scatter C per-head-transposed into vT[s=z][b][h][dh][n].
// MODE 1: dots. z=(s*B+b)*H+h; A=q+off, Bm=k+off; K=64; alpha=g_scalars[12].
// MODE 2: PV. z=b*H+h; K=4096 (s folded); A=P slices, Bm=vT slices.
template<int MODE, int BN, bool TRANSC>
__global__ void __launch_bounds__(256) mma_gemm_k(
    const float* __restrict__ A, const float* __restrict__ Bm, float* __restrict__ C,
    int K, int lda, int ldb, int ldc, long long sB, long long sC,
    const float* __restrict__ bias)
{
    extern __shared__ float smf[];
    constexpr int LDT = 20;               // padded tile row stride (floats)
    constexpr int ASZ = 128 * LDT;        // floats per A stage
    constexpr int BSZ = BN * LDT;
    constexpr int WN = BN / 2;            // warp tile N (warps: 4m x 2n)
    constexpr int NF = WN / 8;            // n-fragments per warp

    int tid = threadIdx.x, lane = tid & 31, wid = tid >> 5;
    int warpM = wid & 3, warpN = wid >> 2;
    int r4 = lane >> 2, c4l = lane & 3;
    int z = blockIdx.z;
    int n0 = blockIdx.x * BN, m0 = blockIdx.y * 128;

    const float *Ab = A, *Bb = Bm;
    float* Cb = C;
    int b_ = 0, h_ = 0;
    if (MODE == 0) {
        Bb = Bm + (long long)z * sB; Cb = C + (long long)z * sC;
    } else if (MODE == 1) {
        int s = z >> 5, r = z & 31; b_ = r >> 4; h_ = r & 15;
        long long off = ((long long)(s * B_ + b_) * N_) * D_ + h_ * DH_;
        Ab = A + off; Bb = Bm + off; Cb = C + ((long long)z << 20);
    } else {
        b_ = z >> 4; h_ = z & 15;
        Cb = C + (long long)b_ * N_ * D_ + h_ * DH_;
    }

    uint32_t smb = smem_u32(smf);
    float acc[2][NF][4];
    #pragma unroll
    for (int mf = 0; mf < 2; mf++)
        #pragma unroll
        for (int nf = 0; nf < NF; nf++)
            #pragma unroll
            for (int i = 0; i < 4; i++) acc[mf][nf][i] = 0.f;

    const int T = K / 16;

    auto issue = [&](int t) {
        const float *ap, *bp; int as_, bs_;
        if (MODE == 2) {
            int s = t >> 6, j0 = (t & 63) * 16;
            long long sl = (long long)((s * B_ + b_) * H_ + h_);
            ap = A + (sl << 20) + (long long)m0 * N_ + j0;
            bp = Bm + sl * ((long long)DH_ * N_) + j0;
            as_ = N_; bs_ = N_;
        } else {
            ap = Ab + (long long)m0 * lda + t * 16;
            bp = Bb + (long long)n0 * ldb + t * 16;
            as_ = lda; bs_ = ldb;
        }
        int buf = t & 1;
        uint32_t sa = smb + buf * ASZ * 4;
        uint32_t sbb = smb + 2 * ASZ * 4 + buf * BSZ * 4;
        #pragma unroll
        for (int i = 0; i < 2; i++) {
            int idx = tid + 256 * i;
            int row = idx >> 2, c4 = (idx & 3) * 4;
            cp16(sa + (row * LDT + c4) * 4, ap + (long long)row * as_ + c4);
        }
        #pragma unroll
        for (int i = 0; i < BN / 64; i++) {
            int idx = tid + 256 * i;
            int row = idx >> 2, c4 = (idx & 3) * 4;
            cp16(sbb + (row * LDT + c4) * 4, bp + (long long)row * bs_ + c4);
        }
        asm volatile("cp.async.commit_group;" ::: "memory");
    };

    issue(0);
    for (int t = 0; t < T; t++) {
        if (t + 1 < T) {
            issue(t + 1);
            asm volatile("cp.async.wait_group 1;" ::: "memory");
        } else {
            asm volatile("cp.async.wait_group 0;" ::: "memory");
        }
        __syncthreads();

        int buf = t & 1;
        const float* As = smf + buf * ASZ;
        const float* Bs = smf + 2 * ASZ + buf * BSZ;
        #pragma unroll
        for (int kk = 0; kk < 16; kk += 8) {
            uint32_t a[2][4], bf[NF][2];
            #pragma unroll
            for (int mf = 0; mf < 2; mf++) {
                int row = warpM * 32 + mf * 16 + r4;
                a[mf][0] = f2tf(As[row * LDT + kk + c4l]);
                a[mf][1] = f2tf(As[(row + 8) * LDT + kk + c4l]);
                a[mf][2] = f2tf(As[row * LDT + kk + c4l + 4]);
                a[mf][3] = f2tf(As[(row + 8) * LDT + kk + c4l + 4]);
            }
            #pragma unroll
            for (int nf = 0; nf < NF; nf++) {
                int col = warpN * WN + nf * 8 + r4;
                bf[nf][0] = f2tf(Bs[col * LDT + kk + c4l]);
                bf[nf][1] = f2tf(Bs[col * LDT + kk + c4l + 4]);
            }
            #pragma unroll
            for (int mf = 0; mf < 2; mf++)
                #pragma unroll
                for (int nf = 0; nf < NF; nf++)
                    mma1688(acc[mf][nf], a[mf], bf[nf]);
        }
        __syncthreads();
    }

    if (TRANSC) {
        // stage C to smem (stride 129 -> conflict-free column reads), then
        // write per-head-transposed into vT with n-coalesced stores.
        float* Cs = smf;   // 128*129 floats
        #pragma unroll
        for (int mf = 0; mf < 2; mf++)
            #pragma unroll
            for (int nf = 0; nf < NF; nf++)
                #pragma unroll
                for (int half = 0; half < 2; half++) {
                    int row = warpM * 32 + mf * 16 + r4 + half * 8;
                    int col = warpN * WN + nf * 8 + c4l * 2;
                    Cs[row * 129 + col]     = acc[mf][nf][half * 2];
                    Cs[row * 129 + col + 1] = acc[mf][nf][half * 2 + 1];
                }
        __syncthreads();
        #pragma unroll
        for (int ei = 0; ei < 16; ei++) {
            int e = wid + 8 * ei;          // local output-feature column
            int ge = n0 + e;
            long long dbase = (((long long)((z * B_) * H_) ) << 16); // placeholder, recomputed below
            #pragma unroll
            for (int q = 0; q < 4; q++) {
                int nl = lane + 32 * q;
                int m = m0 + nl;
                int bb = m >> 10, n = m & 1023;
                (void)dbase;
                C[(((long long)((z * B_ + bb) * H_ + (ge >> 6))) << 16)
                  + (long long)(ge & 63) * N_ + n] = Cs[nl * 129 + e];
            }
        }
    } else {
        float alpha = (MODE == 1) ? g_scalars[12] : 1.0f;
        #pragma unroll
        for (int mf = 0; mf < 2; mf++)
            #pragma unroll
            for (int nf = 0; nf < NF; nf++)
                #pragma unroll
                for (int half = 0; half < 2; half++) {
                    int row = m0 + warpM * 32 + mf * 16 + r4 + half * 8;
                    int col = n0 + warpN * WN + nf * 8 + c4l * 2;
                    float v0 = acc[mf][nf][half * 2] * alpha;
                    float v1 = acc[mf][nf][half * 2 + 1] * alpha;
                    if (bias) { v0 += bias[col]; v1 += bias[col + 1]; }
                    float2 o; o.x = v0; o.y = v1;
                    *(float2*)(Cb + (long long)row * ldc + col) = o;
                }
    }
}

// ---------------- softmax + gate-fold + attn-mean ---------------------------
__global__ void __launch_bounds__(256) softmax_attn_k(float* __restrict__ P,
                                                      float* __restrict__ Aout) {
    int bi = blockIdx.x;
    int b = bi >> 10, i = bi & 1023;
    int tid = threadIdx.x;
    __shared__ float red[8];
    float aacc0 = 0.f, aacc1 = 0.f, aacc2 = 0.f, aacc3 = 0.f;

    for (int s = 0; s < S_; s++) {
        float ga = g_scalars[8 + s];
        float wsb = g_scalars[b * 4 + s];
        for (int h = 0; h < H_; h++) {
            float* row = P + ((long long)((s * B_ + b) * H_ + h) * N_ + i) * N_;
            float v0 = row[tid], v1 = row[tid + 256], v2 = row[tid + 512], v3 = row[tid + 768];
            float mx = fmaxf(fmaxf(v0, v1), fmaxf(v2, v3));
            for (int o = 16; o; o >>= 1) mx = fmaxf(mx, __shfl_xor_sync(0xffffffffu, mx, o));
            if ((tid & 31) == 0) red[tid >> 5] = mx;
            __syncthreads();
            mx = fmaxf(fmaxf(fmaxf(red[0], red[1]), fmaxf(red[2], red[3])),
                       fmaxf(fmaxf(red[4], red[5]), fmaxf(red[6], red[7])));
            __syncthreads();
            v0 = __expf(v0 - mx); v1 = __expf(v1 - mx);
            v2 = __expf(v2 - mx); v3 = __expf(v3 - mx);
            float sm = v0 + v1 + v2 + v3;
            for (int o = 16; o; o >>= 1) sm += __shfl_xor_sync(0xffffffffu, sm, o);
            if ((tid & 31) == 0) red[tid >> 5] = sm;
            __syncthreads();
            sm = red[0] + red[1] + red[2] + red[3] + red[4] + red[5] + red[6] + red[7];
            __syncthreads();
            float inv = 1.0f / sm;
            v0 *= inv; v1 *= inv; v2 *= inv; v3 *= inv;
            aacc0 += ga * v0; aacc1 += ga * v1; aacc2 += ga * v2; aacc3 += ga * v3;
            row[tid] = wsb * v0; row[tid + 256] = wsb * v1;
            row[tid + 512] = wsb * v2; row[tid + 768] = wsb * v3;
        }
    }
    long long base = (long long)bi * N_;
    Aout[base + tid] = aacc0; Aout[base + tid + 256] = aacc1;
    Aout[base + tid + 512] = aacc2; Aout[base + tid + 768] = aacc3;
}

// ---------------- launch ----------------------------------------------------
extern "C" void kernel_launch(void* const* d_in, const int* in_sizes, int n_in,
                              void* d_out, int out_size) {
    const float* x     = (const float*)d_in[0];
    const float* Wq    = (const float*)d_in[1];
    const float* Wk    = (const float*)d_in[2];
    const float* Wv    = (const float*)d_in[3];
    const float* Wg    = (const float*)d_in[4];
    const float* bg    = (const float*)d_in[5];
    const float* Wo    = (const float*)d_in[6];
    const float* bo    = (const float*)d_in[7];
    const float* hyp_w = (const float*)d_in[8];
    const float* temp  = (const float*)d_in[9];
    float* out = (float*)d_out;

    float *q, *k, *vT, *P, *comb;
    cudaGetSymbolAddress((void**)&q, g_q);
    cudaGetSymbolAddress((void**)&k, g_k);
    cudaGetSymbolAddress((void**)&vT, g_vT);
    cudaGetSymbolAddress((void**)&P, g_P);
    cudaGetSymbolAddress((void**)&comb, g_comb);

    const long long DD = (long long)D_ * D_;        // weight per-s stride
    const long long QS = (long long)B_ * N_ * D_;   // qkv per-s stride

    // dynamic smem: pipeline = 2*(128+BN)*20*4 bytes; TRANSC also needs 128*129*4
    const int SM_P128 = 2 * (128 + 128) * 20 * 4;   // 40960
    const int SM_TR   = 128 * 129 * 4;              // 66048
    const int SM_P64  = 2 * (128 + 64) * 20 * 4;    // 30720

    cudaFuncSetAttribute(mma_gemm_k<0, 128, false>, cudaFuncAttributeMaxDynamicSharedMemorySize, SM_P128);
    cudaFuncSetAttribute(mma_gemm_k<0, 128, true >, cudaFuncAttributeMaxDynamicSharedMemorySize, SM_TR);
    cudaFuncSetAttribute(mma_gemm_k<1, 128, false>, cudaFuncAttributeMaxDynamicSharedMemorySize, SM_P128);
    cudaFuncSetAttribute(mma_gemm_k<2, 64,  false>, cudaFuncAttributeMaxDynamicSharedMemorySize, SM_P64);

    colmean_k<<<8, 256>>>(x);
    gate_k<<<1, 256>>>(Wg, bg, hyp_w, temp);

    // Q/K projections: 4 slices of 2048x1024x1024 each
    mma_gemm_k<0, 128, false><<<dim3(8, 16, 4), 256, SM_P128>>>(
        x, Wq, q, 1024, D_, D_, D_, DD, QS, nullptr);
    mma_gemm_k<0, 128, false><<<dim3(8, 16, 4), 256, SM_P128>>>(
        x, Wk, k, 1024, D_, D_, D_, DD, QS, nullptr);
    // V projection written per-head-transposed into vT
    mma_gemm_k<0, 128, true><<<dim3(8, 16, 4), 256, SM_TR>>>(
        x, Wv, vT, 1024, D_, D_, 0, DD, 0, nullptr);

    // dots: 128 slices of 1024x1024x64, alpha = scale/temp
    mma_gemm_k<1, 128, false><<<dim3(8, 8, 128), 256, SM_P128>>>(
        q, k, P, 64, D_, D_, N_, 0, 0, nullptr);

    // softmax + gate-fold + attn-mean -> second half of d_out
    softmax_attn_k<<<B_ * N_, 256>>>(P, out + (long long)B_ * N_ * D_);

    // PV: 32 slices of 1024x64x4096 (s folded into K) -> comb
    mma_gemm_k<2, 64, false><<<dim3(1, 8, 32), 256, SM_P64>>>(
        P, vT, comb, 4096, 0, 0, D_, 0, 0, nullptr);

    // y = comb @ Wo^T + bo -> first half of d_out
    mma_gemm_k<0, 128, false><<<dim3(8, 16, 1), 256, SM_P128>>>(
        comb, Wo, out, 1024, D_, D_, D_, 0, 0, bo);
}

// round 5
// speedup vs baseline: 5.9241x; 1.8207x over previous
#include <cuda_runtime.h>
#include <cuda_fp16.h>
#include <cstdint>

#define S_ 4
#define B_ 2
#define N_ 1024
#define D_ 1024
#define H_ 16
#define DH_ 64

// ---------------- device scratch (no allocations allowed) -------------------
__device__ __half g_xh[B_ * N_ * D_];                       // 4MB
__device__ __half g_wh[13 * 1024 * 1024];                   // Wq(0-3) Wk(4-7) Wv(8-11) Wo(12)
__device__ __half g_qh[S_ * B_ * N_ * D_];                  // 16MB
__device__ __half g_kh[S_ * B_ * N_ * D_];                  // 16MB
__device__ __half g_vTh[S_ * B_ * N_ * D_];                 // [s][b][h][dh][n] 16MB
__device__ __half g_Ph[(size_t)S_ * B_ * H_ * N_ * N_];     // scores/probs 256MB
__device__ __half g_combh[B_ * N_ * D_];                    // 4MB
__device__ float g_meanx[B_ * D_];
__device__ float g_scalars[16];  // [0..7]=gw*coh (b*4+s), [8..11]=gw/H, [12]=scale/temp

// ---------------- helpers ----------------------------------------------------
__device__ __forceinline__ uint32_t smem_u32(const void* p) {
    uint32_t a;
    asm("{ .reg .u64 t; cvta.to.shared.u64 t, %1; cvt.u32.u64 %0, t; }" : "=r"(a) : "l"(p));
    return a;
}
__device__ __forceinline__ void cp16h(uint32_t dst, const __half* src) {
    asm volatile("cp.async.ca.shared.global [%0], [%1], 16;" :: "r"(dst), "l"(src) : "memory");
}
__device__ __forceinline__ void ldm4(uint32_t* r, uint32_t addr) {
    asm volatile("ldmatrix.sync.aligned.m8n8.x4.shared.b16 {%0,%1,%2,%3}, [%4];"
        : "=r"(r[0]), "=r"(r[1]), "=r"(r[2]), "=r"(r[3]) : "r"(addr));
}
__device__ __forceinline__ void mma16816(float* d, const uint32_t* a, uint32_t b0, uint32_t b1) {
    asm volatile(
        "mma.sync.aligned.m16n8k16.row.col.f32.f16.f16.f32 "
        "{%0,%1,%2,%3}, {%4,%5,%6,%7}, {%8,%9}, {%0,%1,%2,%3};"
        : "+f"(d[0]), "+f"(d[1]), "+f"(d[2]), "+f"(d[3])
        : "r"(a[0]), "r"(a[1]), "r"(a[2]), "r"(a[3]), "r"(b0), "r"(b1));
}
__device__ __forceinline__ uint32_t h2u(__half2 h) { return *(uint32_t*)&h; }

// ---------------- prep: round x + weights to fp16 ---------------------------
__global__ void prep_k(const float* __restrict__ x, const float* __restrict__ Wq,
                       const float* __restrict__ Wk, const float* __restrict__ Wv,
                       const float* __restrict__ Wo) {
    long long idx = ((long long)blockIdx.x * 256 + threadIdx.x) * 4;
    const float* src; __half* dst; long long off;
    if (idx < 2097152)        { src = x;  off = idx;            dst = g_xh; }
    else if (idx < 6291456)   { src = Wq; off = idx - 2097152;  dst = g_wh; }
    else if (idx < 10485760)  { src = Wk; off = idx - 6291456;  dst = g_wh + 4194304; }
    else if (idx < 14680064)  { src = Wv; off = idx - 10485760; dst = g_wh + 8388608; }
    else                      { src = Wo; off = idx - 14680064; dst = g_wh + 12582912; }
    float4 v = *(const float4*)(src + off);
    __half2 h0 = __floats2half2_rn(v.x, v.y), h1 = __floats2half2_rn(v.z, v.w);
    uint2 o; o.x = h2u(h0); o.y = h2u(h1);
    *(uint2*)(dst + off) = o;
}

// ---------------- column mean of x over N ----------------------------------
__global__ void colmean_k(const float* __restrict__ x) {
    int idx = blockIdx.x * 256 + threadIdx.x;
    int b = idx >> 10, d = idx & 1023;
    float sum = 0.f;
    const float* xp = x + (long long)b * N_ * D_ + d;
    for (int n = 0; n < N_; n++) sum += xp[(long long)n * D_];
    g_meanx[idx] = sum * (1.0f / N_);
}

// ---------------- gate: coh, gw, fused scalars ------------------------------
__global__ void gate_k(const float* __restrict__ Wg, const float* __restrict__ bg,
                       const float* __restrict__ hyp_w, const float* __restrict__ temp_p) {
    __shared__ float cohs[8];
    int tid = threadIdx.x;
    int w = tid >> 5, lane = tid & 31;
    if (w < 8) {
        int b = w >> 2, s = w & 3;
        float sum = 0.f;
        for (int d = lane; d < D_; d += 32)
            sum += g_meanx[b * D_ + d] * Wg[s * D_ + d];
        for (int o = 16; o; o >>= 1) sum += __shfl_xor_sync(0xffffffffu, sum, o);
        if (lane == 0) cohs[w] = 1.0f / (1.0f + expf(-(sum + bg[s])));
    }
    __syncthreads();
    if (tid == 0) {
        float t = fminf(fmaxf(temp_p[0], 0.1f), 10.0f);
        float e[S_], mx = -1e30f;
        for (int s = 0; s < S_; s++) { e[s] = hyp_w[s] / t; mx = fmaxf(mx, e[s]); }
        float den = 0.f;
        for (int s = 0; s < S_; s++) { e[s] = expf(e[s] - mx); den += e[s]; }
        for (int s = 0; s < S_; s++) {
            float gw = e[s] / den;
            g_scalars[8 + s] = gw / (float)H_;
            for (int b = 0; b < B_; b++)
                g_scalars[b * 4 + s] = gw * cohs[b * 4 + s];
        }
        g_scalars[12] = 0.125f / t;   // DH^-0.5 / temp
    }
}

// ---------------- fp16 HMMA GEMM: C[BM,BN] = A @ B^T ------------------------
// MODE 0: QK proj. z=0..7: w=z>>2 (0=Q,1=K), s=z&3; B=g_wh slice z; out half.
// MODE 4: V proj.  z=s; B=g_wh slice 8+z; out transposed per head into g_vTh.
// MODE 1: dots. z=(s*B+b)*H+h; K=64; alpha=g_scalars[12]; out g_Ph half.
// MODE 2: PV. z=b*H+h; K=4096 (s folded); out g_combh half. BM=BN=64, 128 thr.
// MODE 3: out proj. A=g_combh, B=g_wh slice 12, +bias, out f32 -> d_out.
template<int MODE>
__global__ void __launch_bounds__(MODE == 2 ? 128 : 256) hgemm_k(
    float* __restrict__ outp, const float* __restrict__ bias)
{
    constexpr int BM   = (MODE == 2) ? 64 : 128;
    constexpr int BN   = (MODE == 2) ? 64 : 128;
    constexpr int NWM  = (MODE == 2) ? 2 : 4;
    constexpr int WN   = (MODE == 2) ? 32 : 64;
    constexpr int NB16 = WN / 16;
    constexpr int NFR  = WN / 8;
    constexpr int NT   = (MODE == 1) ? 1 : ((MODE == 2) ? 64 : 16);
    constexpr int BT   = (MODE == 2) ? 128 : 256;
    constexpr int STAGE = (BM + BN) * 128;   // bytes per stage

    extern __shared__ char smem[];
    uint32_t smb = smem_u32(smem);

    int tid = threadIdx.x, lane = tid & 31, wid = tid >> 5;
    int warpM = wid % NWM, warpN = wid / NWM;
    int n0 = blockIdx.x * BN, m0 = blockIdx.y * BM, z = blockIdx.z;

    const __half *Ag = nullptr, *Bg = nullptr;
    int s_ = 0, b_ = 0, h_ = 0, w_ = 0;
    if (MODE == 0) { w_ = z >> 2; s_ = z & 3; Ag = g_xh; Bg = g_wh + ((long long)z << 20); }
    if (MODE == 4) { s_ = z; Ag = g_xh; Bg = g_wh + ((long long)(8 + z) << 20); }
    if (MODE == 1) {
        int r = z & 31; s_ = z >> 5; b_ = r >> 4; h_ = r & 15;
        long long off = ((long long)(s_ * B_ + b_) * N_) * D_ + h_ * DH_;
        Ag = g_qh + off; Bg = g_kh + off;
    }
    if (MODE == 2) { b_ = z >> 4; h_ = z & 15; }
    if (MODE == 3) { Ag = g_combh; Bg = g_wh + (12LL << 20); }

    float acc[2][NFR][4];
    #pragma unroll
    for (int mf = 0; mf < 2; mf++)
        #pragma unroll
        for (int nf = 0; nf < NFR; nf++)
            #pragma unroll
            for (int i = 0; i < 4; i++) acc[mf][nf][i] = 0.f;

    auto issue = [&](int t) {
        const __half *ap, *bp;
        if (MODE == 2) {
            int ss = t >> 4, j0 = (t & 15) * 64;
            long long sl = (long long)((ss * B_ + b_) * H_ + h_);
            ap = g_Ph + (sl << 20) + (long long)m0 * 1024 + j0;
            bp = g_vTh + (sl << 16) + j0;
        } else {
            ap = Ag + (long long)m0 * 1024 + t * 64;
            bp = Bg + (long long)n0 * 1024 + t * 64;
        }
        uint32_t sa  = smb + (t & 1) * STAGE;
        uint32_t sbb = sa + BM * 128;
        #pragma unroll
        for (int i = 0; i < BM * 8 / BT; i++) {
            int c = tid + BT * i, row = c >> 3, ch = c & 7;
            cp16h(sa + ((row * 128 + ch * 16) ^ ((row & 7) << 4)),
                  ap + (long long)row * 1024 + ch * 8);
        }
        #pragma unroll
        for (int i = 0; i < BN * 8 / BT; i++) {
            int c = tid + BT * i, row = c >> 3, ch = c & 7;
            cp16h(sbb + ((row * 128 + ch * 16) ^ ((row & 7) << 4)),
                  bp + (long long)row * 1024 + ch * 8);
        }
        asm volatile("cp.async.commit_group;" ::: "memory");
    };

    issue(0);
    for (int t = 0; t < NT; t++) {
        if (t + 1 < NT) {
            issue(t + 1);
            asm volatile("cp.async.wait_group 1;" ::: "memory");
        } else {
            asm volatile("cp.async.wait_group 0;" ::: "memory");
        }
        __syncthreads();
        uint32_t sa = smb + (t & 1) * STAGE, sbb = sa + BM * 128;
        #pragma unroll
        for (int kk = 0; kk < 4; kk++) {
            uint32_t af[2][4], bf[NB16][4];
            #pragma unroll
            for (int mf = 0; mf < 2; mf++) {
                int row = warpM * 32 + mf * 16 + (lane & 15);
                uint32_t off = row * 128 + kk * 32 + ((lane >> 4) << 4);
                ldm4(af[mf], sa + (off ^ ((row & 7) << 4)));
            }
            #pragma unroll
            for (int nb = 0; nb < NB16; nb++) {
                int row = warpN * WN + nb * 16 + (lane & 15);
                uint32_t off = row * 128 + kk * 32 + ((lane >> 4) << 4);
                ldm4(bf[nb], sbb + (off ^ ((row & 7) << 4)));
            }
            #pragma unroll
            for (int mf = 0; mf < 2; mf++)
                #pragma unroll
                for (int nf = 0; nf < NFR; nf++)
                    mma16816(acc[mf][nf], af[mf], bf[nf >> 1][nf & 1], bf[nf >> 1][(nf & 1) + 2]);
        }
        __syncthreads();
    }

    int r4 = lane >> 2, c4l = lane & 3;

    if (MODE == 0) {
        __half* C = (w_ == 0 ? g_qh : g_kh) + (long long)s_ * (B_ * N_ * D_);
        #pragma unroll
        for (int mf = 0; mf < 2; mf++)
            #pragma unroll
            for (int nf = 0; nf < NFR; nf++)
                #pragma unroll
                for (int hf = 0; hf < 2; hf++) {
                    int row = m0 + warpM * 32 + mf * 16 + r4 + hf * 8;
                    int col = n0 + warpN * WN + nf * 8 + c4l * 2;
                    __half2 hv = __floats2half2_rn(acc[mf][nf][hf * 2], acc[mf][nf][hf * 2 + 1]);
                    *(__half2*)(C + (long long)row * 1024 + col) = hv;
                }
    } else if (MODE == 4) {
        float* Cs = (float*)smem;   // 128 x 129 f32 staging
        #pragma unroll
        for (int mf = 0; mf < 2; mf++)
            #pragma unroll
            for (int nf = 0; nf < NFR; nf++)
                #pragma unroll
                for (int hf = 0; hf < 2; hf++) {
                    int row = warpM * 32 + mf * 16 + r4 + hf * 8;
                    int col = warpN * WN + nf * 8 + c4l * 2;
                    Cs[row * 129 + col]     = acc[mf][nf][hf * 2];
                    Cs[row * 129 + col + 1] = acc[mf][nf][hf * 2 + 1];
                }
        __syncthreads();
        #pragma unroll
        for (int ei = 0; ei < 16; ei++) {
            int e = wid + 8 * ei, ge = n0 + e;
            #pragma unroll
            for (int qq = 0; qq < 4; qq++) {
                int nl = lane + 32 * qq, m = m0 + nl;
                int bb = m >> 10, n = m & 1023;
                g_vTh[(((long long)((s_ * B_ + bb) * H_ + (ge >> 6))) << 16)
                      + (long long)(ge & 63) * 1024 + n] = __float2half_rn(Cs[nl * 129 + e]);
            }
        }
    } else if (MODE == 1) {
        float alpha = g_scalars[12];
        __half* C = g_Ph + ((long long)z << 20);
        #pragma unroll
        for (int mf = 0; mf < 2; mf++)
            #pragma unroll
            for (int nf = 0; nf < NFR; nf++)
                #pragma unroll
                for (int hf = 0; hf < 2; hf++) {
                    int row = m0 + warpM * 32 + mf * 16 + r4 + hf * 8;
                    int col = n0 + warpN * WN + nf * 8 + c4l * 2;
                    __half2 hv = __floats2half2_rn(acc[mf][nf][hf * 2] * alpha,
                                                   acc[mf][nf][hf * 2 + 1] * alpha);
                    *(__half2*)(C + (long long)row * 1024 + col) = hv;
                }
    } else if (MODE == 2) {
        __half* C = g_combh + (long long)b_ * (N_ * D_) + h_ * 64;
        #pragma unroll
        for (int mf = 0; mf < 2; mf++)
            #pragma unroll
            for (int nf = 0; nf < NFR; nf++)
                #pragma unroll
                for (int hf = 0; hf < 2; hf++) {
                    int row = m0 + warpM * 32 + mf * 16 + r4 + hf * 8;
                    int col = warpN * WN + nf * 8 + c4l * 2;
                    __half2 hv = __floats2half2_rn(acc[mf][nf][hf * 2], acc[mf][nf][hf * 2 + 1]);
                    *(__half2*)(C + (long long)row * 1024 + col) = hv;
                }
    } else {   // MODE 3
        #pragma unroll
        for (int mf = 0; mf < 2; mf++)
            #pragma unroll
            for (int nf = 0; nf < NFR; nf++)
                #pragma unroll
                for (int hf = 0; hf < 2; hf++) {
                    int row = m0 + warpM * 32 + mf * 16 + r4 + hf * 8;
                    int col = n0 + warpN * WN + nf * 8 + c4l * 2;
                    float2 o;
                    o.x = acc[mf][nf][hf * 2]     + bias[col];
                    o.y = acc[mf][nf][hf * 2 + 1] + bias[col + 1];
                    *(float2*)(outp + (long long)row * 1024 + col) = o;
                }
    }
}

// ---------------- softmax + gate-fold + attn-mean (fp16 in/out) -------------
__global__ void __launch_bounds__(256) softmax_attn_k(float* __restrict__ Aout) {
    int bi = blockIdx.x;
    int b = bi >> 10, i = bi & 1023;
    int tid = threadIdx.x;
    __shared__ float red[8];
    float a0 = 0.f, a1 = 0.f, a2 = 0.f, a3 = 0.f;

    for (int s = 0; s < S_; s++) {
        float ga = g_scalars[8 + s];
        float wsb = g_scalars[b * 4 + s];
        for (int h = 0; h < H_; h++) {
            __half* row = g_Ph + (((long long)((s * B_ + b) * H_ + h)) << 20) + (long long)i * 1024;
            uint2 u = *(uint2*)(row + 4 * tid);
            __half2 p0 = *(__half2*)&u.x, p1 = *(__half2*)&u.y;
            float2 f0 = __half22float2(p0), f1 = __half22float2(p1);
            float v0 = f0.x, v1 = f0.y, v2 = f1.x, v3 = f1.y;
            float mx = fmaxf(fmaxf(v0, v1), fmaxf(v2, v3));
            for (int o = 16; o; o >>= 1) mx = fmaxf(mx, __shfl_xor_sync(0xffffffffu, mx, o));
            if ((tid & 31) == 0) red[tid >> 5] = mx;
            __syncthreads();
            mx = fmaxf(fmaxf(fmaxf(red[0], red[1]), fmaxf(red[2], red[3])),
                       fmaxf(fmaxf(red[4], red[5]), fmaxf(red[6], red[7])));
            __syncthreads();
            v0 = __expf(v0 - mx); v1 = __expf(v1 - mx);
            v2 = __expf(v2 - mx); v3 = __expf(v3 - mx);
            float sm = v0 + v1 + v2 + v3;
            for (int o = 16; o; o >>= 1) sm += __shfl_xor_sync(0xffffffffu, sm, o);
            if ((tid & 31) == 0) red[tid >> 5] = sm;
            __syncthreads();
            sm = red[0] + red[1] + red[2] + red[3] + red[4] + red[5] + red[6] + red[7];
            __syncthreads();
            float inv = 1.0f / sm;
            v0 *= inv; v1 *= inv; v2 *= inv; v3 *= inv;
            a0 += ga * v0; a1 += ga * v1; a2 += ga * v2; a3 += ga * v3;
            uint2 w;
            w.x = h2u(__floats2half2_rn(wsb * v0, wsb * v1));
            w.y = h2u(__floats2half2_rn(wsb * v2, wsb * v3));
            *(uint2*)(row + 4 * tid) = w;
        }
    }
    float4 ov; ov.x = a0; ov.y = a1; ov.z = a2; ov.w = a3;
    *(float4*)(Aout + (long long)bi * 1024 + 4 * tid) = ov;
}

// ---------------- launch ----------------------------------------------------
extern "C" void kernel_launch(void* const* d_in, const int* in_sizes, int n_in,
                              void* d_out, int out_size) {
    const float* x     = (const float*)d_in[0];
    const float* Wq    = (const float*)d_in[1];
    const float* Wk    = (const float*)d_in[2];
    const float* Wv    = (const float*)d_in[3];
    const float* Wg    = (const float*)d_in[4];
    const float* bg    = (const float*)d_in[5];
    const float* Wo    = (const float*)d_in[6];
    const float* bo    = (const float*)d_in[7];
    const float* hyp_w = (const float*)d_in[8];
    const float* temp  = (const float*)d_in[9];
    float* out = (float*)d_out;

    const int SM_PIPE  = 65536;   // 2 x (128+128)x128
    const int SM_VTR   = 66048;   // max(pipe, 128x129 f32)
    const int SM_DOTS  = 32768;   // single stage
    const int SM_PV    = 32768;   // 2 x (64+64)x128

    cudaFuncSetAttribute(hgemm_k<0>, cudaFuncAttributeMaxDynamicSharedMemorySize, SM_PIPE);
    cudaFuncSetAttribute(hgemm_k<4>, cudaFuncAttributeMaxDynamicSharedMemorySize, SM_VTR);
    cudaFuncSetAttribute(hgemm_k<1>, cudaFuncAttributeMaxDynamicSharedMemorySize, SM_DOTS);
    cudaFuncSetAttribute(hgemm_k<2>, cudaFuncAttributeMaxDynamicSharedMemorySize, SM_PV);
    cudaFuncSetAttribute(hgemm_k<3>, cudaFuncAttributeMaxDynamicSharedMemorySize, SM_PIPE);

    prep_k<<<15360, 256>>>(x, Wq, Wk, Wv, Wo);
    colmean_k<<<8, 256>>>(x);
    gate_k<<<1, 256>>>(Wg, bg, hyp_w, temp);

    // Q & K projections merged: z = 0..7
    hgemm_k<0><<<dim3(8, 16, 8), 256, SM_PIPE>>>(nullptr, nullptr);
    // V projection (transposed per head): z = s
    hgemm_k<4><<<dim3(8, 16, 4), 256, SM_VTR>>>(nullptr, nullptr);
    // dots: 128 slices, K=64, alpha folded, fp16 scores
    hgemm_k<1><<<dim3(8, 8, 128), 256, SM_DOTS>>>(nullptr, nullptr);
    // softmax + gate-fold + attn-mean -> second half of d_out
    softmax_attn_k<<<B_ * N_, 256>>>(out + (long long)B_ * N_ * D_);
    // PV: 32 slices, K=4096 (s folded), BM=BN=64
    hgemm_k<2><<<dim3(1, 16, 32), 128, SM_PV>>>(nullptr, nullptr);
    // out proj: comb @ Wo^T + bo -> first half of d_out (f32)
    hgemm_k<3><<<dim3(8, 16, 1), 256, SM_PIPE>>>(out, bo);
}